// round 1
// baseline (speedup 1.0000x reference)
#include <cuda_runtime.h>
#include <math.h>
#include <float.h>

// ---------------------------------------------------------------------------
// MultiLatentSpaceSimilarity — fp32 baseline
// B=16, C=256, S=1024, 3 groups x 8 splits, L=64, HEADS=8, DH=64, INNER=512
// ---------------------------------------------------------------------------

constexpr int B_ = 16, C_ = 256, S_ = 1024;
constexpr int SPLITS_ = 8, L_ = 64, HEADS_ = 8, DH_ = 64, INNER_ = 512;
constexpr float SCALE_ = 0.125f;                 // DH^-0.5
constexpr int NROWS = B_ * HEADS_ * SPLITS_ * L_; // 65536 softmax rows

// Scratch (static device arrays; no allocation at runtime)
__device__ float g_K[(size_t)B_ * INNER_ * S_];   // [b][n=h*64+d][s]  32 MB
__device__ float g_V[(size_t)B_ * INNER_ * S_];   // [b][n][s]         32 MB
__device__ float g_Q[SPLITS_ * L_ * INNER_];      // [p][l][n]          1 MB
__device__ float g_scores[(size_t)B_ * HEADS_ * SPLITS_ * L_ * S_]; // 256 MB
__device__ float g_heat[B_ * SPLITS_ * S_];       // [b*8+p][s]
__device__ float g_distp[B_ * HEADS_ * SPLITS_];  // per-(b,h,p) partial

// ---------------------------------------------------------------------------
// Projection GEMM: out = A_b^T * W, A_b[c, m] = A[batch*bstride + c*lda + m]
// DST: 0 -> g_K (transposed store [b][n][m]), 1 -> g_V (transposed),
//      2 -> g_Q (normal store [b][m][n])
// Tile 64(m) x 64(n), block 256 threads, 4x4 register tile, K-chunks of 32.
// ---------------------------------------------------------------------------
template <int DST, bool TRANS>
__global__ void proj_kernel(const float* __restrict__ A, size_t bstride,
                            int lda, int M, const float* __restrict__ W)
{
    float* outp = (DST == 0) ? g_K : (DST == 1) ? g_V : g_Q;
    __shared__ float As[32][65]; // [c][m]
    __shared__ float Ws[32][65]; // [c][n]
    int tid = threadIdx.x;
    int txq = tid & 15, tyq = tid >> 4;  // txq -> m quad, tyq -> n quad
    int m0 = blockIdx.x * 64, n0 = blockIdx.y * 64;
    int batch = blockIdx.z;
    const float* Ab = A + (size_t)batch * bstride;

    float acc[4][4] = {};
    for (int c0 = 0; c0 < C_; c0 += 32) {
        for (int idx = tid; idx < 2048; idx += 256) {
            int c = idx >> 6, m = idx & 63;
            As[c][m] = Ab[(size_t)(c0 + c) * lda + m0 + m];
            Ws[c][m] = W[(size_t)(c0 + c) * INNER_ + n0 + m];
        }
        __syncthreads();
        #pragma unroll
        for (int cc = 0; cc < 32; cc++) {
            float av[4], wv[4];
            #pragma unroll
            for (int j = 0; j < 4; j++) av[j] = As[cc][txq * 4 + j];
            #pragma unroll
            for (int i4 = 0; i4 < 4; i4++) wv[i4] = Ws[cc][tyq * 4 + i4];
            #pragma unroll
            for (int i4 = 0; i4 < 4; i4++)
                #pragma unroll
                for (int j = 0; j < 4; j++)
                    acc[i4][j] += wv[i4] * av[j];
        }
        __syncthreads();
    }

    if (TRANS) {
        #pragma unroll
        for (int i4 = 0; i4 < 4; i4++) {
            int n = n0 + tyq * 4 + i4;
            float4 vv = make_float4(acc[i4][0], acc[i4][1], acc[i4][2], acc[i4][3]);
            *(float4*)&outp[((size_t)batch * INNER_ + n) * M + m0 + txq * 4] = vv;
        }
    } else {
        #pragma unroll
        for (int i4 = 0; i4 < 4; i4++)
            #pragma unroll
            for (int j = 0; j < 4; j++) {
                int n = n0 + tyq * 4 + i4;
                int m = m0 + txq * 4 + j;
                outp[((size_t)batch * M + m) * INNER_ + n] = acc[i4][j];
            }
    }
}

// ---------------------------------------------------------------------------
// Scores: scores[b,h,p,l,s] = SCALE * sum_d q[p,l,h*64+d] * K[b][h*64+d][s]
// CTA = (s-tile of 64, bhp), block 256, 4x4 register tile over (l, s).
// ---------------------------------------------------------------------------
__global__ void scores_kernel()
{
    int bhp = blockIdx.y;                 // b*64 + h*8 + p
    int p = bhp & 7;
    int h = (bhp >> 3) & 7;
    int b = bhp >> 6;
    int s0 = blockIdx.x * 64;

    __shared__ float Qs[64][65];  // [l][d]
    __shared__ float Ks[64][65];  // [d][s]

    int tid = threadIdx.x;
    const float* qbase = g_Q + (size_t)p * L_ * INNER_ + h * DH_;
    for (int idx = tid; idx < 4096; idx += 256) {
        int l = idx >> 6, d = idx & 63;
        Qs[l][d] = qbase[(size_t)l * INNER_ + d];
    }
    const float* kbase = g_K + ((size_t)(b * HEADS_ + h) * DH_) * S_ + s0;
    for (int idx = tid; idx < 4096; idx += 256) {
        int d = idx >> 6, s = idx & 63;
        Ks[d][s] = kbase[(size_t)d * S_ + s];
    }
    __syncthreads();

    int txq = tid & 15, tyq = tid >> 4;   // txq -> s quad, tyq -> l quad
    float acc[4][4] = {};
    #pragma unroll
    for (int d = 0; d < 64; d++) {
        float kv[4], qv[4];
        #pragma unroll
        for (int j = 0; j < 4; j++) kv[j] = Ks[d][txq * 4 + j];
        #pragma unroll
        for (int iL = 0; iL < 4; iL++) qv[iL] = Qs[tyq * 4 + iL][d];
        #pragma unroll
        for (int iL = 0; iL < 4; iL++)
            #pragma unroll
            for (int j = 0; j < 4; j++)
                acc[iL][j] += qv[iL] * kv[j];
    }

    float* srow = g_scores + ((size_t)bhp * L_) * S_ + s0;
    #pragma unroll
    for (int iL = 0; iL < 4; iL++) {
        int l = tyq * 4 + iL;
        float4 vv = make_float4(acc[iL][0] * SCALE_, acc[iL][1] * SCALE_,
                                acc[iL][2] * SCALE_, acc[iL][3] * SCALE_);
        *(float4*)&srow[(size_t)l * S_ + txq * 4] = vv;
    }
}

// ---------------------------------------------------------------------------
// Softmax over s (1024) per row; one block (256 threads) per row, in-place.
// ---------------------------------------------------------------------------
__global__ void softmax_kernel()
{
    size_t row = blockIdx.x;
    float4* ptr = (float4*)(g_scores + row * S_);
    int tid = threadIdx.x;
    float4 v = ptr[tid];

    float m = fmaxf(fmaxf(v.x, v.y), fmaxf(v.z, v.w));
    #pragma unroll
    for (int off = 16; off; off >>= 1)
        m = fmaxf(m, __shfl_xor_sync(0xffffffffu, m, off));
    __shared__ float redm[8];
    if ((tid & 31) == 0) redm[tid >> 5] = m;
    __syncthreads();
    float mm = redm[0];
    #pragma unroll
    for (int w = 1; w < 8; w++) mm = fmaxf(mm, redm[w]);

    v.x = expf(v.x - mm); v.y = expf(v.y - mm);
    v.z = expf(v.z - mm); v.w = expf(v.w - mm);
    float s = v.x + v.y + v.z + v.w;
    #pragma unroll
    for (int off = 16; off; off >>= 1)
        s += __shfl_xor_sync(0xffffffffu, s, off);
    __shared__ float reds[8];
    if ((tid & 31) == 0) reds[tid >> 5] = s;
    __syncthreads();
    float tot = 0.f;
    #pragma unroll
    for (int w = 0; w < 8; w++) tot += reds[w];

    float inv = 1.0f / tot;
    v.x *= inv; v.y *= inv; v.z *= inv; v.w *= inv;
    ptr[tid] = v;
}

// ---------------------------------------------------------------------------
// heat[b,p,s] = mean over (h,l) of attn[b,h,p,l,s]
// ---------------------------------------------------------------------------
__global__ void heat_kernel()
{
    int bp = blockIdx.y;
    int p = bp & 7, b = bp >> 3;
    int s = blockIdx.x * 256 + threadIdx.x;
    float acc = 0.f;
    for (int h = 0; h < HEADS_; h++) {
        const float* base =
            g_scores + ((size_t)((b * HEADS_ + h) * SPLITS_ + p)) * L_ * S_ + s;
        #pragma unroll 8
        for (int l = 0; l < L_; l++)
            acc += base[(size_t)l * S_];
    }
    g_heat[(size_t)bp * S_ + s] = acc * (1.0f / (HEADS_ * L_));
}

// ---------------------------------------------------------------------------
// out[l][d] = attn(64x1024) @ V^T; accumulate sum (q - out)^2 per (b,h,p).
// CTA per bhp; block 256; 4x4 register tile; K-loop over s in 64 chunks.
// ---------------------------------------------------------------------------
__global__ void out_dist_kernel()
{
    int bhp = blockIdx.x;
    int p = bhp & 7;
    int h = (bhp >> 3) & 7;
    int b = bhp >> 6;

    __shared__ float As[64][65];  // [l][s]
    __shared__ float Vs[64][65];  // [d][s]
    int tid = threadIdx.x;
    int txq = tid & 15, tyq = tid >> 4;   // txq -> d quad, tyq -> l quad

    const float* arow = g_scores + ((size_t)bhp * L_) * S_;
    const float* vbase = g_V + ((size_t)(b * HEADS_ + h) * DH_) * S_;

    float acc[4][4] = {};
    for (int s0 = 0; s0 < S_; s0 += 64) {
        for (int idx = tid; idx < 4096; idx += 256) {
            int l = idx >> 6, s = idx & 63;
            As[l][s] = arow[(size_t)l * S_ + s0 + s];
        }
        for (int idx = tid; idx < 4096; idx += 256) {
            int d = idx >> 6, s = idx & 63;
            Vs[d][s] = vbase[(size_t)d * S_ + s0 + s];
        }
        __syncthreads();
        #pragma unroll
        for (int s = 0; s < 64; s++) {
            float av[4], vv[4];
            #pragma unroll
            for (int iL = 0; iL < 4; iL++) av[iL] = As[tyq * 4 + iL][s];
            #pragma unroll
            for (int j = 0; j < 4; j++) vv[j] = Vs[txq * 4 + j][s];
            #pragma unroll
            for (int iL = 0; iL < 4; iL++)
                #pragma unroll
                for (int j = 0; j < 4; j++)
                    acc[iL][j] += av[iL] * vv[j];
        }
        __syncthreads();
    }

    const float* qb = g_Q + (size_t)p * L_ * INNER_ + h * DH_;
    float ssum = 0.f;
    #pragma unroll
    for (int iL = 0; iL < 4; iL++) {
        int l = tyq * 4 + iL;
        #pragma unroll
        for (int j = 0; j < 4; j++) {
            int d = txq * 4 + j;
            float diff = qb[(size_t)l * INNER_ + d] - acc[iL][j];
            ssum += diff * diff;
        }
    }
    __shared__ float red[256];
    red[tid] = ssum;
    __syncthreads();
    for (int off = 128; off > 0; off >>= 1) {
        if (tid < off) red[tid] += red[tid + off];
        __syncthreads();
    }
    if (tid == 0) g_distp[bhp] = red[0];
}

// ---------------------------------------------------------------------------
// dist[b, col0 + p] = (sum_h partial) / (L * INNER)
// ---------------------------------------------------------------------------
__global__ void reduce_dist_kernel(float* __restrict__ out, int col0)
{
    int t = threadIdx.x;
    if (t < B_ * SPLITS_) {
        int p = t & 7, b = t >> 3;
        float s = 0.f;
        #pragma unroll
        for (int h = 0; h < HEADS_; h++) s += g_distp[b * 64 + h * 8 + p];
        out[b * 24 + col0 + p] = s * (1.0f / (L_ * INNER_));
    }
}

// ---------------------------------------------------------------------------
// argmax over s of heat[b,p,:]; first index wins ties (matches jnp.argmax).
// Written as float into out[384 + b*24 + col0 + p].
// ---------------------------------------------------------------------------
__global__ void argmax_kernel(float* __restrict__ out, int col0)
{
    int bp = blockIdx.x;
    int p = bp & 7, b = bp >> 3;
    const float* hrow = g_heat + (size_t)bp * S_;
    int tid = threadIdx.x;

    float best = -FLT_MAX;
    int bidx = 0;
    for (int s = tid; s < S_; s += 256) {
        float v = hrow[s];
        if (v > best) { best = v; bidx = s; }   // strict > keeps lowest s per thread
    }
    __shared__ float sv[256];
    __shared__ int si[256];
    sv[tid] = best; si[tid] = bidx;
    __syncthreads();
    for (int off = 128; off > 0; off >>= 1) {
        if (tid < off) {
            bool take = (sv[tid + off] > sv[tid]) ||
                        (sv[tid + off] == sv[tid] && si[tid + off] < si[tid]);
            if (take) { sv[tid] = sv[tid + off]; si[tid] = si[tid + off]; }
        }
        __syncthreads();
    }
    if (tid == 0) out[384 + b * 24 + col0 + p] = (float)si[0];
}

__global__ void zero_kernel(float* o, int n)
{
    int i = blockIdx.x * blockDim.x + threadIdx.x;
    if (i < n) o[i] = 0.f;
}

// ---------------------------------------------------------------------------
extern "C" void kernel_launch(void* const* d_in, const int* in_sizes, int n_in,
                              void* d_out, int out_size)
{
    const float* x      = (const float*)d_in[0];  // (B, C, S)
    const float* protos = (const float*)d_in[1];  // (24, C, L)
    const float* Wq     = (const float*)d_in[2];  // (3, C, INNER)
    const float* Wk     = (const float*)d_in[3];
    const float* Wv     = (const float*)d_in[4];
    float* out = (float*)d_out;

    zero_kernel<<<(out_size + 255) / 256, 256>>>(out, out_size);

    for (int i = 0; i < 3; i++) {
        const float* wq = Wq + (size_t)i * C_ * INNER_;
        const float* wk = Wk + (size_t)i * C_ * INNER_;
        const float* wv = Wv + (size_t)i * C_ * INNER_;

        proj_kernel<0, true><<<dim3(S_ / 64, INNER_ / 64, B_), 256>>>(
            x, (size_t)C_ * S_, S_, S_, wk);
        proj_kernel<1, true><<<dim3(S_ / 64, INNER_ / 64, B_), 256>>>(
            x, (size_t)C_ * S_, S_, S_, wv);
        proj_kernel<2, false><<<dim3(1, INNER_ / 64, SPLITS_), 256>>>(
            protos + (size_t)i * SPLITS_ * C_ * L_, (size_t)C_ * L_, L_, L_, wq);

        scores_kernel<<<dim3(S_ / 64, B_ * HEADS_ * SPLITS_), 256>>>();
        softmax_kernel<<<NROWS, 256>>>();
        heat_kernel<<<dim3(S_ / 256, B_ * SPLITS_), 256>>>();
        out_dist_kernel<<<B_ * HEADS_ * SPLITS_, 256>>>();
        reduce_dist_kernel<<<1, 128>>>(out, i * SPLITS_);
        argmax_kernel<<<B_ * SPLITS_, 256>>>(out, i * SPLITS_);
    }
}

// round 2
// speedup vs baseline: 1.2202x; 1.2202x over previous
#include <cuda_runtime.h>
#include <math.h>
#include <float.h>

// ---------------------------------------------------------------------------
// MultiLatentSpaceSimilarity — fused fp32 + f32x2 packed FMA
// B=16, C=256, S=1024, 3 groups x 8 splits, L=64, HEADS=8, DH=64, INNER=512
// ---------------------------------------------------------------------------

constexpr int B_ = 16, C_ = 256, S_ = 1024;
constexpr int SPLITS_ = 8, L_ = 64, HEADS_ = 8, DH_ = 64, INNER_ = 512;
constexpr float SCALE_ = 0.125f;                 // DH^-0.5

// Scratch (static device arrays; no runtime allocation)
__device__ float g_K[(size_t)B_ * INNER_ * S_];   // [b][n=h*64+d][s]  32 MB
__device__ float g_V[(size_t)B_ * INNER_ * S_];   // [b][n][s]         32 MB
__device__ float g_Q[SPLITS_ * L_ * INNER_];      // [p][l][n]          1 MB
__device__ float g_E[(size_t)B_ * HEADS_ * SPLITS_ * L_ * S_]; // exp(scores) 268 MB
__device__ float g_Z[B_ * HEADS_ * SPLITS_ * L_]; // row sums
__device__ float g_heatp[(size_t)B_ * SPLITS_ * HEADS_ * S_];  // per-h heat partials
__device__ float g_distp[B_ * HEADS_ * SPLITS_];  // per-(b,h,p) dist partial

typedef unsigned long long ull;

// packed fp32x2 fma: d = a*b + d (elementwise on the two fp32 halves)
__device__ __forceinline__ void ffma2(ull& d, ull a, ull b)
{
    asm("fma.rn.f32x2 %0, %1, %2, %0;" : "+l"(d) : "l"(a), "l"(b));
}
__device__ __forceinline__ float2 unpk(ull v)
{
    float2 r;
    asm("mov.b64 {%0, %1}, %2;" : "=f"(r.x), "=f"(r.y) : "l"(v));
    return r;
}

// ---------------------------------------------------------------------------
// Projection GEMM: out = A_b^T * W. 64(m) x 64(n) tile, 256 threads,
// 4(n) x 4(m) per thread via f32x2 pairs along m. W duplicated in smem.
// DST: 0 -> g_K (store [b][n][m]), 1 -> g_V, 2 -> g_Q (store [b][m][n])
// ---------------------------------------------------------------------------
template <int DST, bool TRANS>
__global__ void proj_kernel(const float* __restrict__ A, size_t bstride,
                            int lda, int M, const float* __restrict__ W)
{
    float* outp = (DST == 0) ? g_K : (DST == 1) ? g_V : g_Q;
    __shared__ __align__(16) float As[32][68];   // [c][m]
    __shared__ __align__(16) float Wd[32][132];  // [c][2n] duplicated
    int tid = threadIdx.x;
    int txq = tid & 15, tyq = tid >> 4;          // txq -> m quad, tyq -> n quad
    int m0 = blockIdx.x * 64, n0 = blockIdx.y * 64;
    int batch = blockIdx.z;
    const float* Ab = A + (size_t)batch * bstride;

    ull acc[4][2] = {};                          // [n-sub][m-pair]
    for (int c0 = 0; c0 < C_; c0 += 32) {
        __syncthreads();
        for (int idx = tid; idx < 512; idx += 256) {
            int c = idx >> 4, q = idx & 15;
            *(float4*)&As[c][q * 4] =
                *(const float4*)&Ab[(size_t)(c0 + c) * lda + m0 + q * 4];
            float4 w = *(const float4*)&W[(size_t)(c0 + c) * INNER_ + n0 + q * 4];
            Wd[c][q * 8 + 0] = w.x; Wd[c][q * 8 + 1] = w.x;
            Wd[c][q * 8 + 2] = w.y; Wd[c][q * 8 + 3] = w.y;
            Wd[c][q * 8 + 4] = w.z; Wd[c][q * 8 + 5] = w.z;
            Wd[c][q * 8 + 6] = w.w; Wd[c][q * 8 + 7] = w.w;
        }
        __syncthreads();
        #pragma unroll
        for (int cc = 0; cc < 32; cc++) {
            ulonglong2 am  = *(ulonglong2*)&As[cc][txq * 4];
            ulonglong2 w01 = *(ulonglong2*)&Wd[cc][tyq * 8];
            ulonglong2 w23 = *(ulonglong2*)&Wd[cc][tyq * 8 + 4];
            ffma2(acc[0][0], w01.x, am.x); ffma2(acc[0][1], w01.x, am.y);
            ffma2(acc[1][0], w01.y, am.x); ffma2(acc[1][1], w01.y, am.y);
            ffma2(acc[2][0], w23.x, am.x); ffma2(acc[2][1], w23.x, am.y);
            ffma2(acc[3][0], w23.y, am.x); ffma2(acc[3][1], w23.y, am.y);
        }
    }

    if (TRANS) {
        #pragma unroll
        for (int i4 = 0; i4 < 4; i4++) {
            int n = n0 + tyq * 4 + i4;
            float2 a = unpk(acc[i4][0]), b2 = unpk(acc[i4][1]);
            *(float4*)&outp[((size_t)batch * INNER_ + n) * M + m0 + txq * 4] =
                make_float4(a.x, a.y, b2.x, b2.y);
        }
    } else {
        #pragma unroll
        for (int i4 = 0; i4 < 4; i4++) {
            int n = n0 + tyq * 4 + i4;
            float2 a = unpk(acc[i4][0]), b2 = unpk(acc[i4][1]);
            int m = m0 + txq * 4;
            outp[((size_t)batch * M + m + 0) * INNER_ + n] = a.x;
            outp[((size_t)batch * M + m + 1) * INNER_ + n] = a.y;
            outp[((size_t)batch * M + m + 2) * INNER_ + n] = b2.x;
            outp[((size_t)batch * M + m + 3) * INNER_ + n] = b2.y;
        }
    }
}

// ---------------------------------------------------------------------------
// Kernel A: E[l,s] = exp(SCALE * q.k), Z[l] = sum_s E[l,s].
// CTA per (b,h,p)=1024; 256 threads; 4(l)x4(s) per thread, f32x2 pairs on s.
// Q duplicated in smem ([d][2l]); K chunk [d][s].
// ---------------------------------------------------------------------------
__global__ void scores_kernel()
{
    extern __shared__ float sm[];
    float (*Qd)[132] = (float(*)[132])sm;              // [d][2l] dup
    float (*Ks)[68]  = (float(*)[68])(sm + 64 * 132);  // [d][s]

    int bhp = blockIdx.x;
    int p = bhp & 7, h = (bhp >> 3) & 7, b = bhp >> 6;
    int tid = threadIdx.x;
    int txq = tid & 15, tyq = tid >> 4;                // txq -> s quad, tyq -> l quad

    const float* qbase = g_Q + (size_t)p * L_ * INNER_ + h * DH_;
    for (int idx = tid; idx < 1024; idx += 256) {
        int l = idx >> 4, dq = idx & 15;
        float4 v = *(const float4*)&qbase[(size_t)l * INNER_ + dq * 4];
        Qd[dq * 4 + 0][2 * l] = v.x; Qd[dq * 4 + 0][2 * l + 1] = v.x;
        Qd[dq * 4 + 1][2 * l] = v.y; Qd[dq * 4 + 1][2 * l + 1] = v.y;
        Qd[dq * 4 + 2][2 * l] = v.z; Qd[dq * 4 + 2][2 * l + 1] = v.z;
        Qd[dq * 4 + 3][2 * l] = v.w; Qd[dq * 4 + 3][2 * l + 1] = v.w;
    }

    const float* kbase = g_K + ((size_t)(b * HEADS_ + h) * DH_) * S_;
    float* erow = g_E + (size_t)bhp * L_ * S_;
    float zacc[4] = {0.f, 0.f, 0.f, 0.f};

    for (int s0 = 0; s0 < S_; s0 += 64) {
        __syncthreads();
        for (int idx = tid; idx < 1024; idx += 256) {
            int d = idx >> 4, sq = idx & 15;
            *(float4*)&Ks[d][sq * 4] =
                *(const float4*)&kbase[(size_t)d * S_ + s0 + sq * 4];
        }
        __syncthreads();

        ull acc[4][2] = {};
        #pragma unroll
        for (int d = 0; d < 64; d++) {
            ulonglong2 kv  = *(ulonglong2*)&Ks[d][txq * 4];
            ulonglong2 q01 = *(ulonglong2*)&Qd[d][tyq * 8];
            ulonglong2 q23 = *(ulonglong2*)&Qd[d][tyq * 8 + 4];
            ffma2(acc[0][0], q01.x, kv.x); ffma2(acc[0][1], q01.x, kv.y);
            ffma2(acc[1][0], q01.y, kv.x); ffma2(acc[1][1], q01.y, kv.y);
            ffma2(acc[2][0], q23.x, kv.x); ffma2(acc[2][1], q23.x, kv.y);
            ffma2(acc[3][0], q23.y, kv.x); ffma2(acc[3][1], q23.y, kv.y);
        }
        #pragma unroll
        for (int iL = 0; iL < 4; iL++) {
            float2 e0 = unpk(acc[iL][0]), e1 = unpk(acc[iL][1]);
            float4 e;
            e.x = __expf(e0.x * SCALE_); e.y = __expf(e0.y * SCALE_);
            e.z = __expf(e1.x * SCALE_); e.w = __expf(e1.y * SCALE_);
            zacc[iL] += (e.x + e.y) + (e.z + e.w);
            *(float4*)&erow[(size_t)(tyq * 4 + iL) * S_ + s0 + txq * 4] = e;
        }
    }

    #pragma unroll
    for (int iL = 0; iL < 4; iL++) {
        float z = zacc[iL];
        #pragma unroll
        for (int off = 8; off; off >>= 1)
            z += __shfl_xor_sync(0xffffffffu, z, off);
        if (txq == 0) g_Z[bhp * 64 + tyq * 4 + iL] = z;
    }
}

// ---------------------------------------------------------------------------
// Kernel B: out = (E/Z) @ V^T (64l x 64d); heat[s] = sum_l E[l,s]/Z[l];
// dist partial = sum (q - out)^2. CTA per (b,h,p); E duplicated [s][2l].
// ---------------------------------------------------------------------------
__global__ void out_kernel()
{
    extern __shared__ float sm[];
    float (*Ed)[132] = (float(*)[132])sm;              // [s][2l] dup
    float (*Vt)[68]  = (float(*)[68])(sm + 64 * 132);  // [s][d]
    float* invZs = sm + 64 * 132 + 64 * 68;            // [64]

    int bhp = blockIdx.x;
    int p = bhp & 7, h = (bhp >> 3) & 7, b = bhp >> 6;
    int tid = threadIdx.x;
    int txq = tid & 15, tyq = tid >> 4;                // txq -> d quad, tyq -> l quad

    if (tid < 64) invZs[tid] = 1.0f / g_Z[bhp * 64 + tid];

    const float* erow  = g_E + (size_t)bhp * L_ * S_;
    const float* vbase = g_V + ((size_t)(b * HEADS_ + h) * DH_) * S_;
    float* heat = g_heatp + ((size_t)(b * SPLITS_ + p) * HEADS_ + h) * S_;

    ull acc[4][2] = {};                                // [l-sub][d-pair]
    for (int s0 = 0; s0 < S_; s0 += 64) {
        __syncthreads();
        for (int idx = tid; idx < 1024; idx += 256) {
            int r = idx >> 4, sq = idx & 15;           // r = l for E, d for V
            float4 e = *(const float4*)&erow[(size_t)r * S_ + s0 + sq * 4];
            Ed[sq * 4 + 0][2 * r] = e.x; Ed[sq * 4 + 0][2 * r + 1] = e.x;
            Ed[sq * 4 + 1][2 * r] = e.y; Ed[sq * 4 + 1][2 * r + 1] = e.y;
            Ed[sq * 4 + 2][2 * r] = e.z; Ed[sq * 4 + 2][2 * r + 1] = e.z;
            Ed[sq * 4 + 3][2 * r] = e.w; Ed[sq * 4 + 3][2 * r + 1] = e.w;
            float4 v = *(const float4*)&vbase[(size_t)r * S_ + s0 + sq * 4];
            Vt[sq * 4 + 0][r] = v.x; Vt[sq * 4 + 1][r] = v.y;
            Vt[sq * 4 + 2][r] = v.z; Vt[sq * 4 + 3][r] = v.w;
        }
        __syncthreads();

        #pragma unroll
        for (int s = 0; s < 64; s++) {
            ulonglong2 vv  = *(ulonglong2*)&Vt[s][txq * 4];
            ulonglong2 e01 = *(ulonglong2*)&Ed[s][tyq * 8];
            ulonglong2 e23 = *(ulonglong2*)&Ed[s][tyq * 8 + 4];
            ffma2(acc[0][0], e01.x, vv.x); ffma2(acc[0][1], e01.x, vv.y);
            ffma2(acc[1][0], e01.y, vv.x); ffma2(acc[1][1], e01.y, vv.y);
            ffma2(acc[2][0], e23.x, vv.x); ffma2(acc[2][1], e23.x, vv.y);
            ffma2(acc[3][0], e23.y, vv.x); ffma2(acc[3][1], e23.y, vv.y);
        }

        // heat column sums for this s-chunk (threads 0..63, s = s0 + tid)
        if (tid < 64) {
            float hacc = 0.f;
            #pragma unroll
            for (int l2 = 0; l2 < 32; l2++) {
                float4 e  = *(float4*)&Ed[tid][l2 * 4];   // {e_a,e_a,e_b,e_b}
                float2 iz = *(float2*)&invZs[l2 * 2];
                hacc += e.x * iz.x + e.z * iz.y;
            }
            heat[s0 + tid] = hacc;
        }
    }

    // dist partial
    const float* qb = g_Q + (size_t)p * L_ * INNER_ + h * DH_;
    float ssum = 0.f;
    #pragma unroll
    for (int iL = 0; iL < 4; iL++) {
        int l = tyq * 4 + iL;
        float iz = invZs[l];
        float2 o0 = unpk(acc[iL][0]), o1 = unpk(acc[iL][1]);
        float4 q4 = *(const float4*)&qb[(size_t)l * INNER_ + txq * 4];
        float d0 = q4.x - o0.x * iz;
        float d1 = q4.y - o0.y * iz;
        float d2 = q4.z - o1.x * iz;
        float d3 = q4.w - o1.y * iz;
        ssum += d0 * d0 + d1 * d1 + d2 * d2 + d3 * d3;
    }
    __shared__ float red[256];
    red[tid] = ssum;
    __syncthreads();
    for (int off = 128; off > 0; off >>= 1) {
        if (tid < off) red[tid] += red[tid + off];
        __syncthreads();
    }
    if (tid == 0) g_distp[bhp] = red[0];
}

// ---------------------------------------------------------------------------
// dist[b, col0 + p] = (sum_h partial) / (L * INNER)
// ---------------------------------------------------------------------------
__global__ void reduce_dist_kernel(float* __restrict__ out, int col0)
{
    int t = threadIdx.x;
    if (t < B_ * SPLITS_) {
        int p = t & 7, b = t >> 3;
        float s = 0.f;
        #pragma unroll
        for (int h = 0; h < HEADS_; h++) s += g_distp[b * 64 + h * 8 + p];
        out[b * 24 + col0 + p] = s * (1.0f / (L_ * INNER_));
    }
}

// ---------------------------------------------------------------------------
// argmax over s of sum_h heatp[b,p,h,:]; first index wins ties.
// ---------------------------------------------------------------------------
__global__ void argmax_kernel(float* __restrict__ out, int col0)
{
    int bp = blockIdx.x;
    int p = bp & 7, b = bp >> 3;
    const float* hp = g_heatp + (size_t)bp * HEADS_ * S_;
    int tid = threadIdx.x;

    float best = -FLT_MAX;
    int bidx = 0;
    for (int s = tid; s < S_; s += 256) {
        float v = 0.f;
        #pragma unroll
        for (int h = 0; h < HEADS_; h++) v += hp[(size_t)h * S_ + s];
        if (v > best) { best = v; bidx = s; }
    }
    __shared__ float sv[256];
    __shared__ int si[256];
    sv[tid] = best; si[tid] = bidx;
    __syncthreads();
    for (int off = 128; off > 0; off >>= 1) {
        if (tid < off) {
            bool take = (sv[tid + off] > sv[tid]) ||
                        (sv[tid + off] == sv[tid] && si[tid + off] < si[tid]);
            if (take) { sv[tid] = sv[tid + off]; si[tid] = si[tid + off]; }
        }
        __syncthreads();
    }
    if (tid == 0) out[384 + b * 24 + col0 + p] = (float)si[0];
}

// ---------------------------------------------------------------------------
extern "C" void kernel_launch(void* const* d_in, const int* in_sizes, int n_in,
                              void* d_out, int out_size)
{
    const float* x      = (const float*)d_in[0];  // (B, C, S)
    const float* protos = (const float*)d_in[1];  // (24, C, L)
    const float* Wq     = (const float*)d_in[2];  // (3, C, INNER)
    const float* Wk     = (const float*)d_in[3];
    const float* Wv     = (const float*)d_in[4];
    float* out = (float*)d_out;

    constexpr int A_SMEM = (64 * 132 + 64 * 68) * 4;        // 51200 B
    constexpr int B_SMEM = (64 * 132 + 64 * 68 + 64) * 4;   // 51456 B
    cudaFuncSetAttribute(scores_kernel,
                         cudaFuncAttributeMaxDynamicSharedMemorySize, A_SMEM);
    cudaFuncSetAttribute(out_kernel,
                         cudaFuncAttributeMaxDynamicSharedMemorySize, B_SMEM);

    for (int i = 0; i < 3; i++) {
        const float* wq = Wq + (size_t)i * C_ * INNER_;
        const float* wk = Wk + (size_t)i * C_ * INNER_;
        const float* wv = Wv + (size_t)i * C_ * INNER_;

        proj_kernel<0, true><<<dim3(S_ / 64, INNER_ / 64, B_), 256>>>(
            x, (size_t)C_ * S_, S_, S_, wk);
        proj_kernel<1, true><<<dim3(S_ / 64, INNER_ / 64, B_), 256>>>(
            x, (size_t)C_ * S_, S_, S_, wv);
        proj_kernel<2, false><<<dim3(1, INNER_ / 64, SPLITS_), 256>>>(
            protos + (size_t)i * SPLITS_ * C_ * L_, (size_t)C_ * L_, L_, L_, wq);

        scores_kernel<<<B_ * HEADS_ * SPLITS_, 256, A_SMEM>>>();
        out_kernel<<<B_ * HEADS_ * SPLITS_, 256, B_SMEM>>>();
        reduce_dist_kernel<<<1, 128>>>(out, i * SPLITS_);
        argmax_kernel<<<B_ * SPLITS_, 256>>>(out, i * SPLITS_);
    }
}

// round 3
// speedup vs baseline: 1.4012x; 1.1483x over previous
#include <cuda_runtime.h>
#include <math.h>
#include <float.h>

// ---------------------------------------------------------------------------
// MultiLatentSpaceSimilarity — fp32, f32x2 packed FMA, 8x8 thread tiles,
// warp-uniform broadcast operands (smem broadcast -> crossbar relief)
// B=16, C=256, S=1024, 3 groups x 8 splits, L=64, HEADS=8, DH=64, INNER=512
// ---------------------------------------------------------------------------

constexpr int B_ = 16, C_ = 256, S_ = 1024;
constexpr int SPLITS_ = 8, L_ = 64, HEADS_ = 8, DH_ = 64, INNER_ = 512;
constexpr float SCALE_ = 0.125f;                 // DH^-0.5

// Scratch (static device arrays; no runtime allocation)
__device__ float g_K[(size_t)B_ * INNER_ * S_];   // [b][n=h*64+d][s]  32 MB
__device__ float g_V[(size_t)B_ * INNER_ * S_];   // [b][n][s]         32 MB
__device__ float g_Q[SPLITS_ * L_ * INNER_];      // [p][l][n]          1 MB
__device__ float g_E[(size_t)B_ * HEADS_ * SPLITS_ * L_ * S_]; // exp(scores)
__device__ float g_Zp[B_ * HEADS_ * SPLITS_ * 4 * L_]; // partial row sums
__device__ float g_heatp[(size_t)B_ * SPLITS_ * HEADS_ * S_];  // per-h heat
__device__ float g_distp[B_ * HEADS_ * SPLITS_];  // per-(b,h,p) dist partial

typedef unsigned long long ull;

__device__ __forceinline__ void ffma2(ull& d, ull a, ull b)
{
    asm("fma.rn.f32x2 %0, %1, %2, %0;" : "+l"(d) : "l"(a), "l"(b));
}
__device__ __forceinline__ float2 unpk(ull v)
{
    float2 r;
    asm("mov.b64 {%0, %1}, %2;" : "=f"(r.x), "=f"(r.y) : "l"(v));
    return r;
}

// ---------------------------------------------------------------------------
// K/V projection: out[b][n][m] = sum_c A[b][c][m] * W[c][n]
// CTA tile 256(m) x 64(n); 256 threads: tx=tid&31 -> m (8 each, per-lane),
// wy=tid>>5 -> n (8 each, warp-uniform broadcast). k-chunks of 32.
// ---------------------------------------------------------------------------
template <int DST>
__global__ __launch_bounds__(256) void projKV_kernel(
    const float* __restrict__ A, const float* __restrict__ W)
{
    extern __shared__ float sm[];
    float* As = sm;                 // [32][256]
    float* Wd = sm + 32 * 256;      // [32][132] duplicated pairs

    float* outp = (DST == 0) ? g_K : g_V;
    int tid = threadIdx.x;
    int tx = tid & 31, wy = tid >> 5;
    int m0 = blockIdx.x * 256, n0 = blockIdx.y * 64;
    int batch = blockIdx.z;
    const float* Ab = A + (size_t)batch * C_ * S_;

    ull acc[8][4] = {};                          // [n][m-pair]
    for (int c0 = 0; c0 < C_; c0 += 32) {
        __syncthreads();
        #pragma unroll
        for (int it = 0; it < 8; it++) {
            int idx = tid + it * 256;
            int c = idx >> 6, mq = idx & 63;
            *(float4*)&As[c * 256 + mq * 4] =
                *(const float4*)&Ab[(size_t)(c0 + c) * S_ + m0 + mq * 4];
        }
        #pragma unroll
        for (int it = 0; it < 2; it++) {
            int idx = tid + it * 256;
            int c = idx >> 4, nq = idx & 15;
            float4 w = *(const float4*)&W[(size_t)(c0 + c) * INNER_ + n0 + nq * 4];
            float* wr = &Wd[c * 132 + nq * 8];
            *(float2*)&wr[0] = make_float2(w.x, w.x);
            *(float2*)&wr[2] = make_float2(w.y, w.y);
            *(float2*)&wr[4] = make_float2(w.z, w.z);
            *(float2*)&wr[6] = make_float2(w.w, w.w);
        }
        __syncthreads();
        #pragma unroll 8
        for (int c = 0; c < 32; c++) {
            const float* ar = &As[c * 256 + tx * 8];
            ulonglong2 a01 = *(const ulonglong2*)ar;
            ulonglong2 a23 = *(const ulonglong2*)(ar + 4);
            const float* wr = &Wd[c * 132 + wy * 16];
            ulonglong2 wa = *(const ulonglong2*)wr;
            ulonglong2 wb = *(const ulonglong2*)(wr + 4);
            ulonglong2 wc = *(const ulonglong2*)(wr + 8);
            ulonglong2 wd2 = *(const ulonglong2*)(wr + 12);
            ull wp[8] = {wa.x, wa.y, wb.x, wb.y, wc.x, wc.y, wd2.x, wd2.y};
            ull ap[4] = {a01.x, a01.y, a23.x, a23.y};
            #pragma unroll
            for (int ni = 0; ni < 8; ni++)
                #pragma unroll
                for (int mj = 0; mj < 4; mj++)
                    ffma2(acc[ni][mj], wp[ni], ap[mj]);
        }
    }

    #pragma unroll
    for (int ni = 0; ni < 8; ni++) {
        int n = n0 + wy * 8 + ni;
        float2 f0 = unpk(acc[ni][0]), f1 = unpk(acc[ni][1]);
        float2 f2 = unpk(acc[ni][2]), f3 = unpk(acc[ni][3]);
        float* orow = &outp[((size_t)batch * INNER_ + n) * S_ + m0 + tx * 8];
        *(float4*)&orow[0] = make_float4(f0.x, f0.y, f1.x, f1.y);
        *(float4*)&orow[4] = make_float4(f2.x, f2.y, f3.x, f3.y);
    }
}

// ---------------------------------------------------------------------------
// Q projection (small: 8p x 64l x 512n). Old 4x4 style, adequate.
// out g_Q[p][l][n]
// ---------------------------------------------------------------------------
__global__ void projQ_kernel(const float* __restrict__ A,
                             const float* __restrict__ W)
{
    __shared__ __align__(16) float As[32][68];   // [c][l]
    __shared__ __align__(16) float Wd[32][132];  // [c][2n] dup
    int tid = threadIdx.x;
    int txq = tid & 15, tyq = tid >> 4;
    int n0 = blockIdx.y * 64;
    int p = blockIdx.z;
    const float* Ab = A + (size_t)p * C_ * L_;

    ull acc[4][2] = {};
    for (int c0 = 0; c0 < C_; c0 += 32) {
        __syncthreads();
        for (int idx = tid; idx < 512; idx += 256) {
            int c = idx >> 4, q = idx & 15;
            *(float4*)&As[c][q * 4] =
                *(const float4*)&Ab[(size_t)(c0 + c) * L_ + q * 4];
            float4 w = *(const float4*)&W[(size_t)(c0 + c) * INNER_ + n0 + q * 4];
            Wd[c][q * 8 + 0] = w.x; Wd[c][q * 8 + 1] = w.x;
            Wd[c][q * 8 + 2] = w.y; Wd[c][q * 8 + 3] = w.y;
            Wd[c][q * 8 + 4] = w.z; Wd[c][q * 8 + 5] = w.z;
            Wd[c][q * 8 + 6] = w.w; Wd[c][q * 8 + 7] = w.w;
        }
        __syncthreads();
        #pragma unroll
        for (int cc = 0; cc < 32; cc++) {
            ulonglong2 am  = *(ulonglong2*)&As[cc][txq * 4];
            ulonglong2 w01 = *(ulonglong2*)&Wd[cc][tyq * 8];
            ulonglong2 w23 = *(ulonglong2*)&Wd[cc][tyq * 8 + 4];
            ffma2(acc[0][0], w01.x, am.x); ffma2(acc[0][1], w01.x, am.y);
            ffma2(acc[1][0], w01.y, am.x); ffma2(acc[1][1], w01.y, am.y);
            ffma2(acc[2][0], w23.x, am.x); ffma2(acc[2][1], w23.x, am.y);
            ffma2(acc[3][0], w23.y, am.x); ffma2(acc[3][1], w23.y, am.y);
        }
    }
    #pragma unroll
    for (int i4 = 0; i4 < 4; i4++) {
        int n = n0 + tyq * 4 + i4;
        float2 a = unpk(acc[i4][0]), b2 = unpk(acc[i4][1]);
        int l = txq * 4;
        g_Q[((size_t)p * L_ + l + 0) * INNER_ + n] = a.x;
        g_Q[((size_t)p * L_ + l + 1) * INNER_ + n] = a.y;
        g_Q[((size_t)p * L_ + l + 2) * INNER_ + n] = b2.x;
        g_Q[((size_t)p * L_ + l + 3) * INNER_ + n] = b2.y;
    }
}

// ---------------------------------------------------------------------------
// Scores: E[l,s] = exp(SCALE*q.k), Zp[sq][l] = partial sums over 256 s.
// Grid (4 s-quarters, 1024 bhp). 256 thr: tx=tid&31 -> s (8 each),
// wy=tid>>5 -> l (8 each, warp-uniform). Full depth d=64 in smem.
// ---------------------------------------------------------------------------
__global__ __launch_bounds__(256) void scores_kernel()
{
    extern __shared__ float sm[];
    float* Kt = sm;                 // [64][256]
    float* Qd = sm + 64 * 256;      // [64][132] duplicated pairs

    int sq = blockIdx.x;
    int bhp = blockIdx.y;
    int p = bhp & 7, h = (bhp >> 3) & 7, b = bhp >> 6;
    int s0 = sq * 256;
    int tid = threadIdx.x;
    int tx = tid & 31, wy = tid >> 5;

    const float* kbase = g_K + ((size_t)(b * HEADS_ + h) * DH_) * S_ + s0;
    #pragma unroll
    for (int it = 0; it < 16; it++) {
        int idx = tid + it * 256;
        int d = idx >> 6, sqq = idx & 63;
        *(float4*)&Kt[d * 256 + sqq * 4] =
            *(const float4*)&kbase[(size_t)d * S_ + sqq * 4];
    }
    const float* qbase = g_Q + (size_t)p * L_ * INNER_ + h * DH_;
    #pragma unroll
    for (int it = 0; it < 4; it++) {
        int idx = tid + it * 256;
        int l = idx >> 4, dq = idx & 15;
        float4 q = *(const float4*)&qbase[(size_t)l * INNER_ + dq * 4];
        Qd[(dq * 4 + 0) * 132 + 2 * l] = q.x; Qd[(dq * 4 + 0) * 132 + 2 * l + 1] = q.x;
        Qd[(dq * 4 + 1) * 132 + 2 * l] = q.y; Qd[(dq * 4 + 1) * 132 + 2 * l + 1] = q.y;
        Qd[(dq * 4 + 2) * 132 + 2 * l] = q.z; Qd[(dq * 4 + 2) * 132 + 2 * l + 1] = q.z;
        Qd[(dq * 4 + 3) * 132 + 2 * l] = q.w; Qd[(dq * 4 + 3) * 132 + 2 * l + 1] = q.w;
    }
    __syncthreads();

    ull acc[8][4] = {};                          // [l][s-pair]
    #pragma unroll 8
    for (int d = 0; d < 64; d++) {
        const float* kr = &Kt[d * 256 + tx * 8];
        ulonglong2 k01 = *(const ulonglong2*)kr;
        ulonglong2 k23 = *(const ulonglong2*)(kr + 4);
        const float* qr = &Qd[d * 132 + wy * 16];
        ulonglong2 qa = *(const ulonglong2*)qr;
        ulonglong2 qb = *(const ulonglong2*)(qr + 4);
        ulonglong2 qc = *(const ulonglong2*)(qr + 8);
        ulonglong2 qd2 = *(const ulonglong2*)(qr + 12);
        ull qp[8] = {qa.x, qa.y, qb.x, qb.y, qc.x, qc.y, qd2.x, qd2.y};
        ull kp[4] = {k01.x, k01.y, k23.x, k23.y};
        #pragma unroll
        for (int li = 0; li < 8; li++)
            #pragma unroll
            for (int sj = 0; sj < 4; sj++)
                ffma2(acc[li][sj], qp[li], kp[sj]);
    }

    float* erow = g_E + (size_t)bhp * L_ * S_ + s0;
    #pragma unroll
    for (int li = 0; li < 8; li++) {
        int l = wy * 8 + li;
        float2 a0 = unpk(acc[li][0]), a1 = unpk(acc[li][1]);
        float2 a2 = unpk(acc[li][2]), a3 = unpk(acc[li][3]);
        float e0 = __expf(a0.x * SCALE_), e1 = __expf(a0.y * SCALE_);
        float e2 = __expf(a1.x * SCALE_), e3 = __expf(a1.y * SCALE_);
        float e4 = __expf(a2.x * SCALE_), e5 = __expf(a2.y * SCALE_);
        float e6 = __expf(a3.x * SCALE_), e7 = __expf(a3.y * SCALE_);
        float* ep = &erow[(size_t)l * S_ + tx * 8];
        *(float4*)&ep[0] = make_float4(e0, e1, e2, e3);
        *(float4*)&ep[4] = make_float4(e4, e5, e6, e7);
        float z = ((e0 + e1) + (e2 + e3)) + ((e4 + e5) + (e6 + e7));
        #pragma unroll
        for (int off = 16; off; off >>= 1)
            z += __shfl_xor_sync(0xffffffffu, z, off);
        if (tx == 0) g_Zp[(bhp * 4 + sq) * 64 + l] = z;
    }
}

// ---------------------------------------------------------------------------
// Out: out_unnorm[l,d] = E @ V^T, dist = sum (q - out/Z)^2, heat col sums.
// CTA per bhp; 256 thr = 4 s-slices x (tx=8 d-octets, ly=8 l-octets).
// Each slice covers 256 s in 8 chunks of 32; slice partials reduced in smem.
// ---------------------------------------------------------------------------
__global__ __launch_bounds__(256) void out_kernel()
{
    extern __shared__ float sm[];
    // layout: Ed 4x[32][132], Vt 4x[32][68], buf [64][66], invZ [64]
    float* Ed_all = sm;
    float* Vt_all = sm + 4 * 32 * 132;
    float* buf    = Vt_all + 4 * 32 * 68;
    float* invZs  = buf + 64 * 66;
    __shared__ float red[256];

    int bhp = blockIdx.x;
    int p = bhp & 7, h = (bhp >> 3) & 7, b = bhp >> 6;
    int tid = threadIdx.x;
    int sz = tid >> 6, t6 = tid & 63;
    int tx = t6 & 7, ly = t6 >> 3;
    float* Ed = Ed_all + sz * 32 * 132;
    float* Vt = Vt_all + sz * 32 * 68;

    if (tid < 64) {
        float z = 0.f;
        #pragma unroll
        for (int j = 0; j < 4; j++) z += g_Zp[(bhp * 4 + j) * 64 + tid];
        invZs[tid] = 1.0f / z;
    }

    const float* erow  = g_E + (size_t)bhp * L_ * S_;
    const float* vbase = g_V + ((size_t)(b * HEADS_ + h) * DH_) * S_;
    float* heat = g_heatp + ((size_t)(b * SPLITS_ + p) * HEADS_ + h) * S_;

    ull acc[8][4] = {};                          // [l][d-pair]
    for (int c = 0; c < 8; c++) {
        int s0 = sz * 256 + c * 32;
        __syncthreads();
        #pragma unroll
        for (int it = 0; it < 8; it++) {
            int idx = t6 + it * 64;
            int l = idx >> 3, sqq = idx & 7;     // E: row l, 4 s's
            float4 e = *(const float4*)&erow[(size_t)l * S_ + s0 + sqq * 4];
            Ed[(sqq * 4 + 0) * 132 + 2 * l] = e.x; Ed[(sqq * 4 + 0) * 132 + 2 * l + 1] = e.x;
            Ed[(sqq * 4 + 1) * 132 + 2 * l] = e.y; Ed[(sqq * 4 + 1) * 132 + 2 * l + 1] = e.y;
            Ed[(sqq * 4 + 2) * 132 + 2 * l] = e.z; Ed[(sqq * 4 + 2) * 132 + 2 * l + 1] = e.z;
            Ed[(sqq * 4 + 3) * 132 + 2 * l] = e.w; Ed[(sqq * 4 + 3) * 132 + 2 * l + 1] = e.w;
            float4 v = *(const float4*)&vbase[(size_t)l * S_ + s0 + sqq * 4]; // row d=l
            Vt[(sqq * 4 + 0) * 68 + l] = v.x;
            Vt[(sqq * 4 + 1) * 68 + l] = v.y;
            Vt[(sqq * 4 + 2) * 68 + l] = v.z;
            Vt[(sqq * 4 + 3) * 68 + l] = v.w;
        }
        __syncthreads();

        #pragma unroll 4
        for (int s = 0; s < 32; s++) {
            const float* vr = &Vt[s * 68 + tx * 8];
            ulonglong2 v01 = *(const ulonglong2*)vr;
            ulonglong2 v23 = *(const ulonglong2*)(vr + 4);
            const float* er = &Ed[s * 132 + ly * 16];
            ulonglong2 ea = *(const ulonglong2*)er;
            ulonglong2 eb = *(const ulonglong2*)(er + 4);
            ulonglong2 ec = *(const ulonglong2*)(er + 8);
            ulonglong2 ed2 = *(const ulonglong2*)(er + 12);
            ull ep[8] = {ea.x, ea.y, eb.x, eb.y, ec.x, ec.y, ed2.x, ed2.y};
            ull vp[4] = {v01.x, v01.y, v23.x, v23.y};
            #pragma unroll
            for (int li = 0; li < 8; li++)
                #pragma unroll
                for (int dj = 0; dj < 4; dj++)
                    ffma2(acc[li][dj], ep[li], vp[dj]);
        }

        if (t6 < 32) {
            float hacc = 0.f;
            #pragma unroll 16
            for (int l = 0; l < 64; l++)
                hacc += Ed[t6 * 132 + 2 * l] * invZs[l];
            heat[s0 + t6] = hacc;
        }
    }

    // sequenced cross-slice reduction into buf (deterministic)
    for (int j = 0; j < 4; j++) {
        __syncthreads();
        if (sz == j) {
            #pragma unroll
            for (int li = 0; li < 8; li++) {
                int l = ly * 8 + li;
                #pragma unroll
                for (int dj = 0; dj < 4; dj++) {
                    float2 f = unpk(acc[li][dj]);
                    float* bp = &buf[l * 66 + tx * 8 + dj * 2];
                    if (j == 0) { bp[0] = f.x; bp[1] = f.y; }
                    else        { bp[0] += f.x; bp[1] += f.y; }
                }
            }
        }
    }
    __syncthreads();

    const float* qb = g_Q + (size_t)p * L_ * INNER_ + h * DH_;
    float ssum = 0.f;
    #pragma unroll
    for (int it = 0; it < 16; it++) {
        int idx = tid + it * 256;
        int l = idx >> 6, d = idx & 63;
        float o = buf[l * 66 + d] * invZs[l];
        float diff = qb[(size_t)l * INNER_ + d] - o;
        ssum += diff * diff;
    }
    red[tid] = ssum;
    __syncthreads();
    for (int off = 128; off > 0; off >>= 1) {
        if (tid < off) red[tid] += red[tid + off];
        __syncthreads();
    }
    if (tid == 0) g_distp[bhp] = red[0];
}

// ---------------------------------------------------------------------------
__global__ void reduce_dist_kernel(float* __restrict__ out, int col0)
{
    int t = threadIdx.x;
    if (t < B_ * SPLITS_) {
        int p = t & 7, b = t >> 3;
        float s = 0.f;
        #pragma unroll
        for (int h = 0; h < HEADS_; h++) s += g_distp[b * 64 + h * 8 + p];
        out[b * 24 + col0 + p] = s * (1.0f / (L_ * INNER_));
    }
}

__global__ void argmax_kernel(float* __restrict__ out, int col0)
{
    int bp = blockIdx.x;
    int p = bp & 7, b = bp >> 3;
    const float* hp = g_heatp + (size_t)bp * HEADS_ * S_;
    int tid = threadIdx.x;

    float best = -FLT_MAX;
    int bidx = 0;
    for (int s = tid; s < S_; s += 256) {
        float v = 0.f;
        #pragma unroll
        for (int h = 0; h < HEADS_; h++) v += hp[(size_t)h * S_ + s];
        if (v > best) { best = v; bidx = s; }
    }
    __shared__ float sv[256];
    __shared__ int si[256];
    sv[tid] = best; si[tid] = bidx;
    __syncthreads();
    for (int off = 128; off > 0; off >>= 1) {
        if (tid < off) {
            bool take = (sv[tid + off] > sv[tid]) ||
                        (sv[tid + off] == sv[tid] && si[tid + off] < si[tid]);
            if (take) { sv[tid] = sv[tid + off]; si[tid] = si[tid + off]; }
        }
        __syncthreads();
    }
    if (tid == 0) out[384 + b * 24 + col0 + p] = (float)si[0];
}

// ---------------------------------------------------------------------------
extern "C" void kernel_launch(void* const* d_in, const int* in_sizes, int n_in,
                              void* d_out, int out_size)
{
    const float* x      = (const float*)d_in[0];  // (B, C, S)
    const float* protos = (const float*)d_in[1];  // (24, C, L)
    const float* Wq     = (const float*)d_in[2];  // (3, C, INNER)
    const float* Wk     = (const float*)d_in[3];
    const float* Wv     = (const float*)d_in[4];
    float* out = (float*)d_out;

    constexpr int PROJ_SMEM   = (32 * 256 + 32 * 132) * 4;               // 49664
    constexpr int SCORES_SMEM = (64 * 256 + 64 * 132) * 4;               // 99328
    constexpr int OUT_SMEM    = (4 * 32 * 132 + 4 * 32 * 68 + 64 * 66 + 64) * 4; // 119552

    cudaFuncSetAttribute(projKV_kernel<0>,
                         cudaFuncAttributeMaxDynamicSharedMemorySize, PROJ_SMEM);
    cudaFuncSetAttribute(projKV_kernel<1>,
                         cudaFuncAttributeMaxDynamicSharedMemorySize, PROJ_SMEM);
    cudaFuncSetAttribute(scores_kernel,
                         cudaFuncAttributeMaxDynamicSharedMemorySize, SCORES_SMEM);
    cudaFuncSetAttribute(out_kernel,
                         cudaFuncAttributeMaxDynamicSharedMemorySize, OUT_SMEM);

    for (int i = 0; i < 3; i++) {
        const float* wq = Wq + (size_t)i * C_ * INNER_;
        const float* wk = Wk + (size_t)i * C_ * INNER_;
        const float* wv = Wv + (size_t)i * C_ * INNER_;

        projKV_kernel<0><<<dim3(S_ / 256, INNER_ / 64, B_), 256, PROJ_SMEM>>>(x, wk);
        projKV_kernel<1><<<dim3(S_ / 256, INNER_ / 64, B_), 256, PROJ_SMEM>>>(x, wv);
        projQ_kernel<<<dim3(1, INNER_ / 64, SPLITS_), 256>>>(
            protos + (size_t)i * SPLITS_ * C_ * L_, wq);

        scores_kernel<<<dim3(4, B_ * HEADS_ * SPLITS_), 256, SCORES_SMEM>>>();
        out_kernel<<<B_ * HEADS_ * SPLITS_, 256, OUT_SMEM>>>();
        reduce_dist_kernel<<<1, 128>>>(out, i * SPLITS_);
        argmax_kernel<<<B_ * SPLITS_, 256>>>(out, i * SPLITS_);
    }
}

// round 4
// speedup vs baseline: 1.8174x; 1.2971x over previous
#include <cuda_runtime.h>
#include <math.h>
#include <float.h>

// ---------------------------------------------------------------------------
// MultiLatentSpaceSimilarity — fp32 f32x2, non-duplicated broadcast smem +
// register packing, 2 CTAs/SM everywhere.
// B=16, C=256, S=1024, 3 groups x 8 splits, L=64, HEADS=8, DH=64, INNER=512
// ---------------------------------------------------------------------------

constexpr int B_ = 16, C_ = 256, S_ = 1024;
constexpr int SPLITS_ = 8, L_ = 64, HEADS_ = 8, DH_ = 64, INNER_ = 512;
constexpr float SCALE_ = 0.125f;

// Static device scratch
__device__ float g_K[(size_t)B_ * INNER_ * S_];   // [b][h*64+d][s]
__device__ float g_V[(size_t)B_ * INNER_ * S_];   // [b][h*64+d][s]
__device__ float g_Q[SPLITS_ * L_ * INNER_];      // [p][l][n]
__device__ float g_E[(size_t)B_ * HEADS_ * SPLITS_ * L_ * S_]; // [bhp][l][s]
__device__ float g_Zp[B_ * HEADS_ * SPLITS_ * 4 * L_];         // partial Z
__device__ float g_invZ[B_ * HEADS_ * SPLITS_ * L_];           // 1/Z
__device__ float g_outp[(size_t)4 * 128 * 2 * 64 * 256];       // [sz][bh][rowG][d][row]
__device__ float g_heatp[(size_t)B_ * SPLITS_ * HEADS_ * S_];  // [(b*8+p)*8+h][s]
__device__ float g_distp[B_ * HEADS_ * SPLITS_];

typedef unsigned long long ull;

__device__ __forceinline__ void ffma2(ull& d, ull a, ull b)
{
    asm("fma.rn.f32x2 %0, %1, %2, %0;" : "+l"(d) : "l"(a), "l"(b));
}
__device__ __forceinline__ float2 unpk(ull v)
{
    float2 r;
    asm("mov.b64 {%0, %1}, %2;" : "=f"(r.x), "=f"(r.y) : "l"(v));
    return r;
}
__device__ __forceinline__ ull pack2(float v)
{
    ull r;
    asm("mov.b64 %0, {%1, %1};" : "=l"(r) : "f"(v));
    return r;
}
// load 8 broadcast floats (warp-uniform) and pack to 8 {v,v} pairs
__device__ __forceinline__ void ld_bcast8(const float* p, ull* w)
{
    float4 b0 = *(const float4*)p;
    float4 b1 = *(const float4*)(p + 4);
    w[0] = pack2(b0.x); w[1] = pack2(b0.y); w[2] = pack2(b0.z); w[3] = pack2(b0.w);
    w[4] = pack2(b1.x); w[5] = pack2(b1.y); w[6] = pack2(b1.z); w[7] = pack2(b1.w);
}

// ---------------------------------------------------------------------------
// K/V projection: out[b][n][m] = sum_c A[b][c][m] * W[c][n]
// Tile 256(m) x 64(n); tx -> m (8/lane), wy -> n (8/warp, broadcast).
// ---------------------------------------------------------------------------
template <int DST>
__global__ __launch_bounds__(256, 2) void projKV_kernel(
    const float* __restrict__ A, const float* __restrict__ W)
{
    extern __shared__ float sm[];
    float* As = sm;                 // [32][256]
    float* Ws = sm + 32 * 256;      // [32][68]

    float* outp = (DST == 0) ? g_K : g_V;
    int tid = threadIdx.x;
    int tx = tid & 31, wy = tid >> 5;
    int m0 = blockIdx.x * 256, n0 = blockIdx.y * 64;
    int batch = blockIdx.z;
    const float* Ab = A + (size_t)batch * C_ * S_;

    ull acc[8][4] = {};                          // [n][m-pair]
    for (int c0 = 0; c0 < C_; c0 += 32) {
        __syncthreads();
        #pragma unroll
        for (int it = 0; it < 8; it++) {
            int idx = tid + it * 256;
            int c = idx >> 6, mq = idx & 63;
            *(float4*)&As[c * 256 + mq * 4] =
                *(const float4*)&Ab[(size_t)(c0 + c) * S_ + m0 + mq * 4];
        }
        #pragma unroll
        for (int it = 0; it < 2; it++) {
            int idx = tid + it * 256;
            int c = idx >> 4, nq = idx & 15;
            *(float4*)&Ws[c * 68 + nq * 4] =
                *(const float4*)&W[(size_t)(c0 + c) * INNER_ + n0 + nq * 4];
        }
        __syncthreads();
        #pragma unroll 8
        for (int c = 0; c < 32; c++) {
            const float* ar = &As[c * 256 + tx * 8];
            ulonglong2 a01 = *(const ulonglong2*)ar;
            ulonglong2 a23 = *(const ulonglong2*)(ar + 4);
            ull ap[4] = {a01.x, a01.y, a23.x, a23.y};
            ull wp[8];
            ld_bcast8(&Ws[c * 68 + wy * 8], wp);
            #pragma unroll
            for (int ni = 0; ni < 8; ni++)
                #pragma unroll
                for (int mj = 0; mj < 4; mj++)
                    ffma2(acc[ni][mj], wp[ni], ap[mj]);
        }
    }

    #pragma unroll
    for (int ni = 0; ni < 8; ni++) {
        int n = n0 + wy * 8 + ni;
        float2 f0 = unpk(acc[ni][0]), f1 = unpk(acc[ni][1]);
        float2 f2 = unpk(acc[ni][2]), f3 = unpk(acc[ni][3]);
        float* orow = &outp[((size_t)batch * INNER_ + n) * S_ + m0 + tx * 8];
        *(float4*)&orow[0] = make_float4(f0.x, f0.y, f1.x, f1.y);
        *(float4*)&orow[4] = make_float4(f2.x, f2.y, f3.x, f3.y);
    }
}

// ---------------------------------------------------------------------------
// Q projection (small). out g_Q[p][l][n]
// ---------------------------------------------------------------------------
__global__ void projQ_kernel(const float* __restrict__ A,
                             const float* __restrict__ W)
{
    __shared__ __align__(16) float As[32][68];   // [c][l]
    __shared__ __align__(16) float Wd[32][132];  // [c][2n] dup
    int tid = threadIdx.x;
    int txq = tid & 15, tyq = tid >> 4;
    int n0 = blockIdx.y * 64;
    int p = blockIdx.z;
    const float* Ab = A + (size_t)p * C_ * L_;

    ull acc[4][2] = {};
    for (int c0 = 0; c0 < C_; c0 += 32) {
        __syncthreads();
        for (int idx = tid; idx < 512; idx += 256) {
            int c = idx >> 4, q = idx & 15;
            *(float4*)&As[c][q * 4] =
                *(const float4*)&Ab[(size_t)(c0 + c) * L_ + q * 4];
            float4 w = *(const float4*)&W[(size_t)(c0 + c) * INNER_ + n0 + q * 4];
            Wd[c][q * 8 + 0] = w.x; Wd[c][q * 8 + 1] = w.x;
            Wd[c][q * 8 + 2] = w.y; Wd[c][q * 8 + 3] = w.y;
            Wd[c][q * 8 + 4] = w.z; Wd[c][q * 8 + 5] = w.z;
            Wd[c][q * 8 + 6] = w.w; Wd[c][q * 8 + 7] = w.w;
        }
        __syncthreads();
        #pragma unroll
        for (int cc = 0; cc < 32; cc++) {
            ulonglong2 am  = *(ulonglong2*)&As[cc][txq * 4];
            ulonglong2 w01 = *(ulonglong2*)&Wd[cc][tyq * 8];
            ulonglong2 w23 = *(ulonglong2*)&Wd[cc][tyq * 8 + 4];
            ffma2(acc[0][0], w01.x, am.x); ffma2(acc[0][1], w01.x, am.y);
            ffma2(acc[1][0], w01.y, am.x); ffma2(acc[1][1], w01.y, am.y);
            ffma2(acc[2][0], w23.x, am.x); ffma2(acc[2][1], w23.x, am.y);
            ffma2(acc[3][0], w23.y, am.x); ffma2(acc[3][1], w23.y, am.y);
        }
    }
    #pragma unroll
    for (int i4 = 0; i4 < 4; i4++) {
        int n = n0 + tyq * 4 + i4;
        float2 a = unpk(acc[i4][0]), b2 = unpk(acc[i4][1]);
        int l = txq * 4;
        g_Q[((size_t)p * L_ + l + 0) * INNER_ + n] = a.x;
        g_Q[((size_t)p * L_ + l + 1) * INNER_ + n] = a.y;
        g_Q[((size_t)p * L_ + l + 2) * INNER_ + n] = b2.x;
        g_Q[((size_t)p * L_ + l + 3) * INNER_ + n] = b2.y;
    }
}

// ---------------------------------------------------------------------------
// Scores: E[l,s]=exp(SCALE*q.k), Zp partial sums. Grid (4 sq, 1024 bhp).
// tx -> s (8/lane), wy -> l (8/warp, broadcast). d tiled 2x32.
// ---------------------------------------------------------------------------
__global__ __launch_bounds__(256, 2) void scores_kernel()
{
    extern __shared__ float sm[];
    float* Kt = sm;                 // [32][256]
    float* Qs = sm + 32 * 256;      // [32][68]  (Qs[d][l])

    int sq = blockIdx.x;
    int bhp = blockIdx.y;
    int p = bhp & 7, h = (bhp >> 3) & 7, b = bhp >> 6;
    int s0 = sq * 256;
    int tid = threadIdx.x;
    int tx = tid & 31, wy = tid >> 5;

    const float* kbase = g_K + ((size_t)(b * HEADS_ + h) * DH_) * S_ + s0;
    const float* qbase = g_Q + (size_t)p * L_ * INNER_ + h * DH_;

    ull acc[8][4] = {};                          // [l][s-pair]
    for (int d0 = 0; d0 < 64; d0 += 32) {
        __syncthreads();
        #pragma unroll
        for (int it = 0; it < 8; it++) {
            int idx = tid + it * 256;
            int d = idx >> 6, sqq = idx & 63;
            *(float4*)&Kt[d * 256 + sqq * 4] =
                *(const float4*)&kbase[(size_t)(d0 + d) * S_ + sqq * 4];
        }
        #pragma unroll
        for (int it = 0; it < 2; it++) {
            int idx = tid + it * 256;
            int dq = idx & 7, l = idx >> 3;
            float4 q = *(const float4*)&qbase[(size_t)l * INNER_ + d0 + dq * 4];
            Qs[(dq * 4 + 0) * 68 + l] = q.x;
            Qs[(dq * 4 + 1) * 68 + l] = q.y;
            Qs[(dq * 4 + 2) * 68 + l] = q.z;
            Qs[(dq * 4 + 3) * 68 + l] = q.w;
        }
        __syncthreads();
        #pragma unroll 8
        for (int d = 0; d < 32; d++) {
            const float* kr = &Kt[d * 256 + tx * 8];
            ulonglong2 k01 = *(const ulonglong2*)kr;
            ulonglong2 k23 = *(const ulonglong2*)(kr + 4);
            ull kp[4] = {k01.x, k01.y, k23.x, k23.y};
            ull qp[8];
            ld_bcast8(&Qs[d * 68 + wy * 8], qp);
            #pragma unroll
            for (int li = 0; li < 8; li++)
                #pragma unroll
                for (int sj = 0; sj < 4; sj++)
                    ffma2(acc[li][sj], qp[li], kp[sj]);
        }
    }

    float* erow = g_E + (size_t)bhp * L_ * S_ + s0;
    #pragma unroll
    for (int li = 0; li < 8; li++) {
        int l = wy * 8 + li;
        float2 a0 = unpk(acc[li][0]), a1 = unpk(acc[li][1]);
        float2 a2 = unpk(acc[li][2]), a3 = unpk(acc[li][3]);
        float e0 = __expf(a0.x * SCALE_), e1 = __expf(a0.y * SCALE_);
        float e2 = __expf(a1.x * SCALE_), e3 = __expf(a1.y * SCALE_);
        float e4 = __expf(a2.x * SCALE_), e5 = __expf(a2.y * SCALE_);
        float e6 = __expf(a3.x * SCALE_), e7 = __expf(a3.y * SCALE_);
        float* ep = &erow[(size_t)l * S_ + tx * 8];
        *(float4*)&ep[0] = make_float4(e0, e1, e2, e3);
        *(float4*)&ep[4] = make_float4(e4, e5, e6, e7);
        float z = ((e0 + e1) + (e2 + e3)) + ((e4 + e5) + (e6 + e7));
        #pragma unroll
        for (int off = 16; off; off >>= 1)
            z += __shfl_xor_sync(0xffffffffu, z, off);
        if (tx == 0) g_Zp[(bhp * 4 + sq) * 64 + l] = z;
    }
}

// ---------------------------------------------------------------------------
// invZ[bhp*64+l] = 1 / sum_j Zp[(bhp*4+j)*64+l]
// ---------------------------------------------------------------------------
__global__ void invz_kernel()
{
    int i = blockIdx.x * 256 + threadIdx.x;     // 65536 total
    int bhp = i >> 6, l = i & 63;
    float z = 0.f;
    #pragma unroll
    for (int j = 0; j < 4; j++) z += g_Zp[(bhp * 4 + j) * 64 + l];
    g_invZ[i] = 1.0f / z;
}

// ---------------------------------------------------------------------------
// Out slices: rows = 256 (4 p's x 64 l, shared V), d = 64, s-slice = 256.
// Grid (2 rowG, 4 sz, 128 bh). tx -> rows (8/lane, E side),
// wy -> d (8/warp, broadcast V). Also writes heat for this slice's s range.
// Partial accumulators -> g_outp[sz][bh][rowG][d][row] (smem-transposed).
// ---------------------------------------------------------------------------
__global__ __launch_bounds__(256, 2) void out_slice_kernel()
{
    extern __shared__ float sm[];
    float* Es    = sm;                       // [32][260]  Es[s][row]
    float* Vs    = sm + 32 * 260;            // [32][68]   Vs[s][d]
    float* invZs = sm + 32 * 260 + 32 * 68;  // [256] (4p x 64l)
    // buf for transposed output reuses Es region: [64 d][68]

    int rowG = blockIdx.x;                   // 0..1 (p groups of 4)
    int sz   = blockIdx.y;                   // 0..3 (s slices of 256)
    int bh   = blockIdx.z;                   // b*8+h
    int b = bh >> 3, h = bh & 7;
    int tid = threadIdx.x;
    int tx = tid & 31, wy = tid >> 5;

    {
        int p_loc = tid >> 6, l = tid & 63;
        int bhp = bh * 8 + rowG * 4 + p_loc;
        invZs[tid] = g_invZ[bhp * 64 + l];
    }

    const float* vbase = g_V + ((size_t)(b * HEADS_ + h) * DH_) * S_;
    size_t ebase = ((size_t)(bh * 8 + rowG * 4)) * L_ * S_;

    ull acc[8][4] = {};                      // [d][row-pair]
    for (int c = 0; c < 8; c++) {
        int s0 = sz * 256 + c * 32;
        __syncthreads();
        // E tile: 256 rows x 32 s, transposed into Es[s][row]
        #pragma unroll
        for (int it = 0; it < 8; it++) {
            int idx = tid + it * 256;
            int sq4 = idx & 7, r = idx >> 3;       // r: 0..255
            float4 e = *(const float4*)&g_E[ebase + (size_t)r * S_ + s0 + sq4 * 4];
            Es[(sq4 * 4 + 0) * 260 + r] = e.x;
            Es[(sq4 * 4 + 1) * 260 + r] = e.y;
            Es[(sq4 * 4 + 2) * 260 + r] = e.z;
            Es[(sq4 * 4 + 3) * 260 + r] = e.w;
        }
        // V tile: 64 d x 32 s, transposed into Vs[s][d]
        #pragma unroll
        for (int it = 0; it < 2; it++) {
            int idx = tid + it * 256;
            int sq4 = idx & 7, d = idx >> 3;
            float4 v = *(const float4*)&vbase[(size_t)d * S_ + s0 + sq4 * 4];
            Vs[(sq4 * 4 + 0) * 68 + d] = v.x;
            Vs[(sq4 * 4 + 1) * 68 + d] = v.y;
            Vs[(sq4 * 4 + 2) * 68 + d] = v.z;
            Vs[(sq4 * 4 + 3) * 68 + d] = v.w;
        }
        __syncthreads();

        #pragma unroll 8
        for (int s = 0; s < 32; s++) {
            const float* er = &Es[s * 260 + tx * 8];
            ulonglong2 e01 = *(const ulonglong2*)er;
            ulonglong2 e23 = *(const ulonglong2*)(er + 4);
            ull ep[4] = {e01.x, e01.y, e23.x, e23.y};
            ull vp[8];
            ld_bcast8(&Vs[s * 68 + wy * 8], vp);
            #pragma unroll
            for (int di = 0; di < 8; di++)
                #pragma unroll
                for (int rj = 0; rj < 4; rj++)
                    ffma2(acc[di][rj], vp[di], ep[rj]);
        }

        // heat for this chunk: threads 0..127 -> (s_loc, p_loc)
        if (tid < 128) {
            int s_loc = tid & 31, p_loc = tid >> 5;
            float hacc = 0.f;
            #pragma unroll 16
            for (int l = 0; l < 64; l++)
                hacc += Es[s_loc * 260 + p_loc * 64 + l] * invZs[p_loc * 64 + l];
            int p = rowG * 4 + p_loc;
            g_heatp[((size_t)(b * SPLITS_ + p) * HEADS_ + h) * S_ + s0 + s_loc] = hacc;
        }
    }

    // transpose acc -> buf[d][row64] per row-quarter, write coalesced
    float* buf = Es;  // reuse (needs [64][68] = 4352 floats)
    float* outBase = g_outp +
        (((size_t)(sz * 128 + bh) * 2 + rowG) * 64) * 256;
    for (int q = 0; q < 4; q++) {
        __syncthreads();
        if ((tx >> 3) == q) {
            int rl0 = (tx & 7) * 8;              // local row base within quarter
            #pragma unroll
            for (int di = 0; di < 8; di++) {
                int d = wy * 8 + di;
                #pragma unroll
                for (int rj = 0; rj < 4; rj++) {
                    float2 f = unpk(acc[di][rj]);
                    *(float2*)&buf[d * 68 + rl0 + 2 * rj] = f;
                }
            }
        }
        __syncthreads();
        #pragma unroll
        for (int it = 0; it < 4; it++) {
            int idx = tid + it * 256;
            int d = idx >> 4, r4 = idx & 15;
            float4 v = *(float4*)&buf[d * 68 + r4 * 4];
            *(float4*)&outBase[(size_t)d * 256 + q * 64 + r4 * 4] = v;
        }
    }
}

// ---------------------------------------------------------------------------
// Finish: per bhp, sum 4 slice partials, normalize, dist = sum (q-out)^2.
// ---------------------------------------------------------------------------
__global__ void finish_kernel()
{
    int bhp = blockIdx.x;
    int p = bhp & 7, h = (bhp >> 3) & 7, b = bhp >> 6;
    int bh = b * 8 + h;
    int rowG = p >> 2, p_loc = p & 3;
    int tid = threadIdx.x;

    const float* qb = g_Q + (size_t)p * L_ * INNER_ + h * DH_;
    float ssum = 0.f;
    #pragma unroll
    for (int it = 0; it < 16; it++) {
        int idx = tid + it * 256;
        int d = idx >> 6, l = idx & 63;
        float v = 0.f;
        #pragma unroll
        for (int sz = 0; sz < 4; sz++)
            v += g_outp[(((size_t)(sz * 128 + bh) * 2 + rowG) * 64 + d) * 256 +
                        p_loc * 64 + l];
        float o = v * g_invZ[bhp * 64 + l];
        float diff = qb[(size_t)l * INNER_ + d] - o;
        ssum += diff * diff;
    }
    __shared__ float red[256];
    red[tid] = ssum;
    __syncthreads();
    for (int off = 128; off > 0; off >>= 1) {
        if (tid < off) red[tid] += red[tid + off];
        __syncthreads();
    }
    if (tid == 0) g_distp[bhp] = red[0];
}

// ---------------------------------------------------------------------------
__global__ void reduce_dist_kernel(float* __restrict__ out, int col0)
{
    int t = threadIdx.x;
    if (t < B_ * SPLITS_) {
        int p = t & 7, b = t >> 3;
        float s = 0.f;
        #pragma unroll
        for (int h = 0; h < HEADS_; h++) s += g_distp[b * 64 + h * 8 + p];
        out[b * 24 + col0 + p] = s * (1.0f / (L_ * INNER_));
    }
}

__global__ void argmax_kernel(float* __restrict__ out, int col0)
{
    int bp = blockIdx.x;
    int p = bp & 7, b = bp >> 3;
    const float* hp = g_heatp + (size_t)bp * HEADS_ * S_;
    int tid = threadIdx.x;

    float best = -FLT_MAX;
    int bidx = 0;
    for (int s = tid; s < S_; s += 256) {
        float v = 0.f;
        #pragma unroll
        for (int h = 0; h < HEADS_; h++) v += hp[(size_t)h * S_ + s];
        if (v > best) { best = v; bidx = s; }
    }
    __shared__ float sv[256];
    __shared__ int si[256];
    sv[tid] = best; si[tid] = bidx;
    __syncthreads();
    for (int off = 128; off > 0; off >>= 1) {
        if (tid < off) {
            bool take = (sv[tid + off] > sv[tid]) ||
                        (sv[tid + off] == sv[tid] && si[tid + off] < si[tid]);
            if (take) { sv[tid] = sv[tid + off]; si[tid] = si[tid + off]; }
        }
        __syncthreads();
    }
    if (tid == 0) out[384 + b * 24 + col0 + p] = (float)si[0];
}

// ---------------------------------------------------------------------------
extern "C" void kernel_launch(void* const* d_in, const int* in_sizes, int n_in,
                              void* d_out, int out_size)
{
    const float* x      = (const float*)d_in[0];
    const float* protos = (const float*)d_in[1];
    const float* Wq     = (const float*)d_in[2];
    const float* Wk     = (const float*)d_in[3];
    const float* Wv     = (const float*)d_in[4];
    float* out = (float*)d_out;

    constexpr int PROJ_SMEM   = (32 * 256 + 32 * 68) * 4;            // 41472
    constexpr int SCORES_SMEM = (32 * 256 + 32 * 68) * 4;            // 41472
    constexpr int OUT_SMEM    = (32 * 260 + 32 * 68 + 256) * 4;      // 42992

    cudaFuncSetAttribute(projKV_kernel<0>,
                         cudaFuncAttributeMaxDynamicSharedMemorySize, PROJ_SMEM);
    cudaFuncSetAttribute(projKV_kernel<1>,
                         cudaFuncAttributeMaxDynamicSharedMemorySize, PROJ_SMEM);
    cudaFuncSetAttribute(scores_kernel,
                         cudaFuncAttributeMaxDynamicSharedMemorySize, SCORES_SMEM);
    cudaFuncSetAttribute(out_slice_kernel,
                         cudaFuncAttributeMaxDynamicSharedMemorySize, OUT_SMEM);

    for (int i = 0; i < 3; i++) {
        const float* wq = Wq + (size_t)i * C_ * INNER_;
        const float* wk = Wk + (size_t)i * C_ * INNER_;
        const float* wv = Wv + (size_t)i * C_ * INNER_;

        projKV_kernel<0><<<dim3(S_ / 256, INNER_ / 64, B_), 256, PROJ_SMEM>>>(x, wk);
        projKV_kernel<1><<<dim3(S_ / 256, INNER_ / 64, B_), 256, PROJ_SMEM>>>(x, wv);
        projQ_kernel<<<dim3(1, INNER_ / 64, SPLITS_), 256>>>(
            protos + (size_t)i * SPLITS_ * C_ * L_, wq);

        scores_kernel<<<dim3(4, B_ * HEADS_ * SPLITS_), 256, SCORES_SMEM>>>();
        invz_kernel<<<256, 256>>>();
        out_slice_kernel<<<dim3(2, 4, 128), 256, OUT_SMEM>>>();
        finish_kernel<<<B_ * HEADS_ * SPLITS_, 256>>>();
        reduce_dist_kernel<<<1, 128>>>(out, i * SPLITS_);
        argmax_kernel<<<B_ * SPLITS_, 256>>>(out, i * SPLITS_);
    }
}